// round 1
// baseline (speedup 1.0000x reference)
#include <cuda_runtime.h>
#include <math.h>

// Problem constants
static constexpr int NB   = 256;
static constexpr int NS   = 512;
static constexpr int NH   = 512;
static constexpr int NE   = 512;
static constexpr int NV   = 50257;
static constexpr int NENC = 1024;   // 2*H

// Scratch (static device globals; no allocation allowed)
__device__ float g_pgen[NB];
__device__ float g_xT[NH * NB];     // x transposed: [k][b]
__device__ int   g_ids_is64;

// ---------------------------------------------------------------------------
// K0a: transpose x [B,H] -> xT [H,B] (tiny, 512 KB)
// ---------------------------------------------------------------------------
__global__ void transpose_x_kernel(const float* __restrict__ x) {
    int idx = blockIdx.x * blockDim.x + threadIdx.x;   // over B*H
    if (idx < NB * NH) {
        int b = idx / NH;
        int k = idx % NH;
        g_xT[k * NB + b] = x[idx];
    }
}

// ---------------------------------------------------------------------------
// K0b: detect whether input_ids buffer is int64 or int32.
// If int64 (little-endian), every odd 32-bit word is a zero high-half
// (values in [0, 50257)). If int32, those words are random vocab ids.
// Deterministic for a given input.
// ---------------------------------------------------------------------------
__global__ void detect_ids_kernel(const int* __restrict__ ids32) {
    int tid = threadIdx.x;            // 256 threads
    int nz = 0;
    for (int i = tid; i < 4096; i += 256)
        nz |= (ids32[2 * i + 1] != 0);
    nz = __syncthreads_or(nz);
    if (tid == 0) g_ids_is64 = nz ? 0 : 1;
}

// ---------------------------------------------------------------------------
// Reductions
// ---------------------------------------------------------------------------
__device__ __forceinline__ float warp_reduce_max(float v) {
    #pragma unroll
    for (int o = 16; o > 0; o >>= 1) v = fmaxf(v, __shfl_xor_sync(0xffffffffu, v, o));
    return v;
}
__device__ __forceinline__ float warp_reduce_sum(float v) {
    #pragma unroll
    for (int o = 16; o > 0; o >>= 1) v += __shfl_xor_sync(0xffffffffu, v, o);
    return v;
}

// ---------------------------------------------------------------------------
// K1: context_state = sum_s attn[b,s] * enc[s,b,:]  (streams 537 MB)
//     then p_gen[b] = sigmoid([hidden, embed, context] . pgen_w + pgen_b)
// One block per batch row b, 256 threads, each owns 4 consecutive ENC elems.
// ---------------------------------------------------------------------------
__global__ void ctx_pgen_kernel(const float* __restrict__ attn,
                                const float* __restrict__ enc,
                                const float* __restrict__ hidden,
                                const float* __restrict__ embed,
                                const float* __restrict__ pgen_w,
                                const float* __restrict__ pgen_b) {
    const int b = blockIdx.x;
    const int tid = threadIdx.x;     // 256
    __shared__ float s_attn[NS];
    __shared__ float red[8];

    for (int i = tid; i < NS; i += 256) s_attn[i] = attn[b * NS + i];
    __syncthreads();

    float4 acc = make_float4(0.f, 0.f, 0.f, 0.f);
    #pragma unroll 4
    for (int s = 0; s < NS; s++) {
        const float a = s_attn[s];
        const float4 e = reinterpret_cast<const float4*>(
            enc + ((size_t)s * NB + b) * NENC)[tid];
        acc.x += a * e.x; acc.y += a * e.y; acc.z += a * e.z; acc.w += a * e.w;
    }

    // p_gen dot product: feat = [hidden(512), embed(512), context(1024)]
    float dot = 0.f;
    {
        const int i0 = 2 * tid;
        dot += hidden[b * NH + i0]     * pgen_w[i0];
        dot += hidden[b * NH + i0 + 1] * pgen_w[i0 + 1];
        dot += embed[b * NE + i0]      * pgen_w[NH + i0];
        dot += embed[b * NE + i0 + 1]  * pgen_w[NH + i0 + 1];
        const float* pwc = pgen_w + NH + NE + 4 * tid;
        dot += acc.x * pwc[0] + acc.y * pwc[1] + acc.z * pwc[2] + acc.w * pwc[3];
    }
    dot = warp_reduce_sum(dot);
    if ((tid & 31) == 0) red[tid >> 5] = dot;
    __syncthreads();
    if (tid == 0) {
        float t = 0.f;
        #pragma unroll
        for (int i = 0; i < 8; i++) t += red[i];
        t += pgen_b[0];
        g_pgen[b] = 1.f / (1.f + __expf(-t));
    }
}

// ---------------------------------------------------------------------------
// K2: logits = x @ proj_w^T + proj_b   -> written to d_out
// Tiled SIMT fp32 GEMM: block tile 64(M) x 128(N), BK=16, 256 threads,
// 4x8 per-thread microtile. xT gives coalesced M-major loads of x.
// ---------------------------------------------------------------------------
static constexpr int BM = 64;
static constexpr int BN = 128;
static constexpr int BK = 16;

__global__ __launch_bounds__(256, 3)
void gemm_logits_kernel(const float* __restrict__ W,      // [V, H]
                        const float* __restrict__ bias,   // [V]
                        float* __restrict__ out) {        // [B, V]
    __shared__ float xs[BK][BM + 1];    // stride 65
    __shared__ float ws[BK][BN + 1];    // stride 129

    const int tid = threadIdx.x;
    const int bn0 = blockIdx.x * BN;
    const int bm0 = blockIdx.y * BM;
    const int tm0 = (tid >> 4) * 4;     // 0..60
    const int tn0 = (tid & 15) * 8;     // 0..120

    float acc[4][8] = {};

    for (int k0 = 0; k0 < NH; k0 += BK) {
        // load xs: 16x64 = 1024 elems, 4 per thread, coalesced from g_xT
        #pragma unroll
        for (int i = 0; i < 4; i++) {
            int idx = tid + 256 * i;
            int k = idx >> 6;
            int m = idx & 63;
            xs[k][m] = g_xT[(k0 + k) * NB + bm0 + m];
        }
        // load ws: 16x128 = 2048 elems via float4 along K, 2 f4 per thread
        #pragma unroll
        for (int i = 0; i < 2; i++) {
            int idx = tid * 2 + i;      // 0..511
            int n = idx >> 2;
            int k4 = idx & 3;
            int v = bn0 + n;
            float4 w4;
            if (v < NV)
                w4 = *reinterpret_cast<const float4*>(W + (size_t)v * NH + k0 + k4 * 4);
            else
                w4 = make_float4(0.f, 0.f, 0.f, 0.f);
            ws[k4 * 4 + 0][n] = w4.x;
            ws[k4 * 4 + 1][n] = w4.y;
            ws[k4 * 4 + 2][n] = w4.z;
            ws[k4 * 4 + 3][n] = w4.w;
        }
        __syncthreads();

        #pragma unroll
        for (int k = 0; k < BK; k++) {
            float xr[4], wr[8];
            #pragma unroll
            for (int i = 0; i < 4; i++) xr[i] = xs[k][tm0 + i];
            #pragma unroll
            for (int j = 0; j < 8; j++) wr[j] = ws[k][tn0 + j];
            #pragma unroll
            for (int i = 0; i < 4; i++)
                #pragma unroll
                for (int j = 0; j < 8; j++)
                    acc[i][j] += xr[i] * wr[j];
        }
        __syncthreads();
    }

    #pragma unroll
    for (int i = 0; i < 4; i++) {
        const size_t mrow = (size_t)(bm0 + tm0 + i) * NV;
        #pragma unroll
        for (int j = 0; j < 8; j++) {
            int v = bn0 + tn0 + j;
            if (v < NV) out[mrow + v] = acc[i][j] + bias[v];
        }
    }
}

// ---------------------------------------------------------------------------
// K3: fused per-row softmax + p_gen mix + scatter-add + log.
// One block per batch row; the whole 50257-float row lives in SMEM (~197 KB).
// ---------------------------------------------------------------------------
__global__ void finalize_kernel(float* __restrict__ out,
                                const float* __restrict__ attn,
                                const void* __restrict__ ids_raw) {
    extern __shared__ float row[];      // NV floats
    __shared__ float red[32];
    __shared__ float s_bcast;

    const int b = blockIdx.x;
    const int tid = threadIdx.x;        // 1024
    float* o = out + (size_t)b * NV;

    // pass 1: load row into smem + running max
    float m = -INFINITY;
    for (int v = tid; v < NV; v += 1024) {
        float t = o[v];
        row[v] = t;
        m = fmaxf(m, t);
    }
    m = warp_reduce_max(m);
    if ((tid & 31) == 0) red[tid >> 5] = m;
    __syncthreads();
    if (tid < 32) {
        float t = warp_reduce_max(red[tid]);
        if (tid == 0) s_bcast = t;
    }
    __syncthreads();
    m = s_bcast;

    // pass 2: sum of exp
    float sum = 0.f;
    for (int v = tid; v < NV; v += 1024) sum += __expf(row[v] - m);
    sum = warp_reduce_sum(sum);
    __syncthreads();                    // protect red reuse
    if ((tid & 31) == 0) red[tid >> 5] = sum;
    __syncthreads();
    if (tid < 32) {
        float t = warp_reduce_sum(red[tid]);
        if (tid == 0) s_bcast = t;
    }
    __syncthreads();
    sum = s_bcast;

    const float pg = g_pgen[b];
    const float scale = pg / sum;

    // pass 3: vocab_dist_ in smem
    for (int v = tid; v < NV; v += 1024) row[v] = __expf(row[v] - m) * scale;
    __syncthreads();

    // scatter: 512 entries per row, smem atomics
    if (tid < NS) {
        int id;
        if (g_ids_is64)
            id = (int)reinterpret_cast<const long long*>(ids_raw)[(size_t)b * NS + tid];
        else
            id = reinterpret_cast<const int*>(ids_raw)[(size_t)b * NS + tid];
        atomicAdd(&row[id], (1.f - pg) * attn[b * NS + tid]);
    }
    __syncthreads();

    // pass 4: log(+eps) and write out
    for (int v = tid; v < NV; v += 1024) o[v] = logf(row[v] + 1e-40f);
}

// ---------------------------------------------------------------------------
// Launch
// ---------------------------------------------------------------------------
extern "C" void kernel_launch(void* const* d_in, const int* in_sizes, int n_in,
                              void* d_out, int out_size) {
    const float* x      = (const float*)d_in[0];
    const float* embed  = (const float*)d_in[1];
    const float* hidden = (const float*)d_in[2];
    const float* enc    = (const float*)d_in[3];
    const float* attn   = (const float*)d_in[4];
    const void*  ids    = d_in[5];
    const float* proj_w = (const float*)d_in[6];
    const float* proj_b = (const float*)d_in[7];
    const float* pgen_w = (const float*)d_in[8];
    const float* pgen_b = (const float*)d_in[9];
    float* out = (float*)d_out;

    transpose_x_kernel<<<(NB * NH + 255) / 256, 256>>>(x);
    detect_ids_kernel<<<1, 256>>>((const int*)ids);
    ctx_pgen_kernel<<<NB, 256>>>(attn, enc, hidden, embed, pgen_w, pgen_b);

    dim3 g2((NV + BN - 1) / BN, NB / BM);
    gemm_logits_kernel<<<g2, 256>>>(proj_w, proj_b, out);

    const int smem_bytes = NV * sizeof(float);
    cudaFuncSetAttribute(finalize_kernel,
                         cudaFuncAttributeMaxDynamicSharedMemorySize, smem_bytes);
    finalize_kernel<<<NB, 1024, smem_bytes>>>(out, attn, ids);
}

// round 8
// speedup vs baseline: 2.2927x; 2.2927x over previous
#include <cuda_runtime.h>
#include <cuda_bf16.h>
#include <math.h>

// Problem constants
static constexpr int NB   = 256;
static constexpr int NS   = 512;
static constexpr int NH   = 512;
static constexpr int NE   = 512;
static constexpr int NV   = 50257;
static constexpr int NENC = 1024;   // 2*H

static constexpr int SCHUNKS = 4;

// Scratch
__device__ float g_pgen[NB];
__device__ float g_dotp[SCHUNKS * NB];
__device__ int   g_ids_is64;

// ---------------------------------------------------------------------------
// helpers
// ---------------------------------------------------------------------------
__device__ __forceinline__ unsigned smem_u32(const void* p) {
    unsigned a;
    asm("{ .reg .u64 t; cvta.to.shared.u64 t, %1; cvt.u32.u64 %0, t; }"
        : "=r"(a) : "l"(p));
    return a;
}
__device__ __forceinline__ float warp_reduce_max(float v) {
    #pragma unroll
    for (int o = 16; o > 0; o >>= 1) v = fmaxf(v, __shfl_xor_sync(0xffffffffu, v, o));
    return v;
}
__device__ __forceinline__ float warp_reduce_sum(float v) {
    #pragma unroll
    for (int o = 16; o > 0; o >>= 1) v += __shfl_xor_sync(0xffffffffu, v, o);
    return v;
}

__device__ __forceinline__ void ldsm_x4(unsigned* r, unsigned addr) {
    asm volatile("ldmatrix.sync.aligned.m8n8.x4.shared.b16 {%0,%1,%2,%3}, [%4];"
                 : "=r"(r[0]), "=r"(r[1]), "=r"(r[2]), "=r"(r[3]) : "r"(addr));
}
__device__ __forceinline__ void mma_bf16(float* d, const unsigned* a, const unsigned* b) {
    asm volatile(
        "mma.sync.aligned.m16n8k16.row.col.f32.bf16.bf16.f32 "
        "{%0,%1,%2,%3}, {%4,%5,%6,%7}, {%8,%9}, {%0,%1,%2,%3};"
        : "+f"(d[0]), "+f"(d[1]), "+f"(d[2]), "+f"(d[3])
        : "r"(a[0]), "r"(a[1]), "r"(a[2]), "r"(a[3]), "r"(b[0]), "r"(b[1]));
}

// fp32x4 -> bf16 hi/lo, store as uint2 pairs
__device__ __forceinline__ void cvt_store_hilo(char* base, int hi_off, int lo_off,
                                               unsigned off, float4 w) {
    __nv_bfloat16 h0 = __float2bfloat16(w.x);
    __nv_bfloat16 h1 = __float2bfloat16(w.y);
    __nv_bfloat16 h2 = __float2bfloat16(w.z);
    __nv_bfloat16 h3 = __float2bfloat16(w.w);
    __nv_bfloat16 l0 = __float2bfloat16(w.x - __bfloat162float(h0));
    __nv_bfloat16 l1 = __float2bfloat16(w.y - __bfloat162float(h1));
    __nv_bfloat16 l2 = __float2bfloat16(w.z - __bfloat162float(h2));
    __nv_bfloat16 l3 = __float2bfloat16(w.w - __bfloat162float(h3));
    uint2 hv, lv;
    hv.x = (unsigned)__bfloat16_as_ushort(h0) | ((unsigned)__bfloat16_as_ushort(h1) << 16);
    hv.y = (unsigned)__bfloat16_as_ushort(h2) | ((unsigned)__bfloat16_as_ushort(h3) << 16);
    lv.x = (unsigned)__bfloat16_as_ushort(l0) | ((unsigned)__bfloat16_as_ushort(l1) << 16);
    lv.y = (unsigned)__bfloat16_as_ushort(l2) | ((unsigned)__bfloat16_as_ushort(l3) << 16);
    *reinterpret_cast<uint2*>(base + hi_off + off) = hv;
    *reinterpret_cast<uint2*>(base + lo_off + off) = lv;
}

// ---------------------------------------------------------------------------
// K0: int64-vs-int32 probe for input_ids
// ---------------------------------------------------------------------------
__global__ void detect_ids_kernel(const int* __restrict__ ids32) {
    int tid = threadIdx.x;
    int nz = 0;
    for (int i = tid; i < 4096; i += 256)
        nz |= (ids32[2 * i + 1] != 0);
    nz = __syncthreads_or(nz);
    if (tid == 0) g_ids_is64 = nz ? 0 : 1;
}

// ---------------------------------------------------------------------------
// K1a: partial context dot for p_gen (streams 537 MB)
// ---------------------------------------------------------------------------
__global__ void ctx_partial_kernel(const float* __restrict__ attn,
                                   const float* __restrict__ enc,
                                   const float* __restrict__ pgen_w) {
    const int b = blockIdx.x;
    const int chunk = blockIdx.y;
    const int tid = threadIdx.x;
    const int s0 = chunk * (NS / SCHUNKS);
    __shared__ float s_attn[NS / SCHUNKS];
    __shared__ float red[8];

    for (int i = tid; i < NS / SCHUNKS; i += 256) s_attn[i] = attn[b * NS + s0 + i];
    __syncthreads();

    float4 acc = make_float4(0.f, 0.f, 0.f, 0.f);
    #pragma unroll 4
    for (int s = 0; s < NS / SCHUNKS; s++) {
        const float a = s_attn[s];
        const float4 e = reinterpret_cast<const float4*>(
            enc + ((size_t)(s0 + s) * NB + b) * NENC)[tid];
        acc.x += a * e.x; acc.y += a * e.y; acc.z += a * e.z; acc.w += a * e.w;
    }
    const float* pwc = pgen_w + NH + NE + 4 * tid;
    float dot = acc.x * pwc[0] + acc.y * pwc[1] + acc.z * pwc[2] + acc.w * pwc[3];
    dot = warp_reduce_sum(dot);
    if ((tid & 31) == 0) red[tid >> 5] = dot;
    __syncthreads();
    if (tid == 0) {
        float t = 0.f;
        #pragma unroll
        for (int i = 0; i < 8; i++) t += red[i];
        g_dotp[chunk * NB + b] = t;
    }
}

// ---------------------------------------------------------------------------
// K1b: p_gen
// ---------------------------------------------------------------------------
__global__ void pgen_kernel(const float* __restrict__ hidden,
                            const float* __restrict__ embed,
                            const float* __restrict__ pgen_w,
                            const float* __restrict__ pgen_b) {
    const int b = blockIdx.x;
    const int tid = threadIdx.x;
    __shared__ float red[8];
    const int i0 = 2 * tid;
    float dot = hidden[b * NH + i0]     * pgen_w[i0]
              + hidden[b * NH + i0 + 1] * pgen_w[i0 + 1]
              + embed[b * NE + i0]      * pgen_w[NH + i0]
              + embed[b * NE + i0 + 1]  * pgen_w[NH + i0 + 1];
    dot = warp_reduce_sum(dot);
    if ((tid & 31) == 0) red[tid >> 5] = dot;
    __syncthreads();
    if (tid == 0) {
        float t = 0.f;
        #pragma unroll
        for (int i = 0; i < 8; i++) t += red[i];
        #pragma unroll
        for (int c = 0; c < SCHUNKS; c++) t += g_dotp[c * NB + b];
        t += pgen_b[0];
        g_pgen[b] = 1.f / (1.f + __expf(-t));
    }
}

// ---------------------------------------------------------------------------
// K2: logits via mma.sync bf16 hi/lo-split GEMM.
// CTA tile 128(M)x128(N)x32(K), 8 warps (2Mx4N), warp tile 64x32.
// Smem rows padded to 80B -> conflict-free ldmatrix. Double-buffered.
// ---------------------------------------------------------------------------
static constexpr int BM = 128, BN = 128, BK = 32;
static constexpr int TSTR = 80;             // bytes per 32-bf16 row (64B data + 16B pad)
static constexpr int TILE = BM * TSTR;      // 10240 B
static constexpr int BUF  = 4 * TILE;       // Ahi,Alo,Bhi,Blo
static constexpr int GSMEM = 2 * BUF;       // 81920 B

__global__ __launch_bounds__(256)
void gemm_mma_kernel(const float* __restrict__ X,     // [B, H]
                     const float* __restrict__ W,     // [V, H]
                     const float* __restrict__ bias,  // [V]
                     float* __restrict__ out) {       // [B, V]
    extern __shared__ char sm[];
    __shared__ float s_bias[BN];
    const unsigned smb = smem_u32(sm);
    const int tid  = threadIdx.x;
    const int lane = tid & 31;
    const int wid  = tid >> 5;
    const int m_base = blockIdx.x * BM;     // 0 or 128
    const int n_base = blockIdx.y * BN;
    const int wm = (wid >> 2) * 64;
    const int wn = (wid & 3) * 32;

    float acc[4][4][4] = {};
    float4 stA[4], stB[4];

    // gmem load of one K-chunk into staging regs
    auto ldg = [&](int k0) {
        #pragma unroll
        for (int i = 0; i < 4; i++) {
            int idx = i * 256 + tid;
            int r = idx >> 3, c = idx & 7;
            stA[i] = *reinterpret_cast<const float4*>(X + (size_t)(m_base + r) * NH + k0 + c * 4);
            int v = n_base + r;
            stB[i] = (v < NV)
                ? *reinterpret_cast<const float4*>(W + (size_t)v * NH + k0 + c * 4)
                : make_float4(0.f, 0.f, 0.f, 0.f);
        }
    };
    // convert + store staging regs into smem buffer bsel
    auto sts = [&](int bsel) {
        char* base = sm + bsel * BUF;
        #pragma unroll
        for (int i = 0; i < 4; i++) {
            int idx = i * 256 + tid;
            int r = idx >> 3, c = idx & 7;
            unsigned off = r * TSTR + c * 8;
            cvt_store_hilo(base, 0,        TILE,     off, stA[i]);
            cvt_store_hilo(base, 2 * TILE, 3 * TILE, off, stB[i]);
        }
    };
    auto compute = [&](int bsel) {
        const unsigned Ah = smb + bsel * BUF;
        const unsigned Bh = Ah + 2 * TILE;
        const int arow = wm + (lane & 15);
        const int nrow = wn + (lane & 7) + ((lane & 16) ? 8 : 0);
        #pragma unroll
        for (int kk = 0; kk < BK; kk += 16) {
            const unsigned akb = (kk + ((lane & 16) ? 8 : 0)) * 2;
            const unsigned bkb = (kk + ((lane & 8)  ? 8 : 0)) * 2;
            unsigned ah[4][4], al[4][4], bh[4][2], bl[4][2];
            #pragma unroll
            for (int mt = 0; mt < 4; mt++) {
                unsigned ad = Ah + (unsigned)(arow + mt * 16) * TSTR + akb;
                ldsm_x4(ah[mt], ad);
                ldsm_x4(al[mt], ad + TILE);
            }
            #pragma unroll
            for (int jp = 0; jp < 2; jp++) {
                unsigned bd = Bh + (unsigned)(nrow + jp * 16) * TSTR + bkb;
                unsigned r[4];
                ldsm_x4(r, bd);
                bh[jp * 2][0] = r[0]; bh[jp * 2][1] = r[1];
                bh[jp * 2 + 1][0] = r[2]; bh[jp * 2 + 1][1] = r[3];
                ldsm_x4(r, bd + TILE);
                bl[jp * 2][0] = r[0]; bl[jp * 2][1] = r[1];
                bl[jp * 2 + 1][0] = r[2]; bl[jp * 2 + 1][1] = r[3];
            }
            #pragma unroll
            for (int mt = 0; mt < 4; mt++)
                #pragma unroll
                for (int nt = 0; nt < 4; nt++) {
                    mma_bf16(acc[mt][nt], ah[mt], bh[nt]);
                    mma_bf16(acc[mt][nt], ah[mt], bl[nt]);
                    mma_bf16(acc[mt][nt], al[mt], bh[nt]);
                }
        }
    };

    ldg(0);
    sts(0);
    __syncthreads();
    #pragma unroll 1
    for (int ck = 1; ck <= NH / BK; ck++) {
        if (ck < NH / BK) ldg(ck * BK);
        compute((ck - 1) & 1);
        if (ck < NH / BK) sts(ck & 1);
        __syncthreads();
    }

    // epilogue
    for (int i = tid; i < BN; i += 256) {
        int v = n_base + i;
        s_bias[i] = (v < NV) ? bias[v] : 0.f;
    }
    __syncthreads();

    const int g  = lane >> 2;
    const int t2 = (lane & 3) * 2;
    #pragma unroll
    for (int mt = 0; mt < 4; mt++) {
        const int m0 = m_base + wm + mt * 16 + g;
        float* row0 = out + (size_t)m0 * NV;
        float* row1 = out + (size_t)(m0 + 8) * NV;
        #pragma unroll
        for (int nt = 0; nt < 4; nt++) {
            const int ncol = wn + nt * 8 + t2;
            const int v = n_base + ncol;
            if (v < NV) {
                const float b0 = s_bias[ncol];
                row0[v] = acc[mt][nt][0] + b0;
                row1[v] = acc[mt][nt][2] + b0;
                if (v + 1 < NV) {
                    const float b1 = s_bias[ncol + 1];
                    row0[v + 1] = acc[mt][nt][1] + b1;
                    row1[v + 1] = acc[mt][nt][3] + b1;
                }
            }
        }
    }
}

// ---------------------------------------------------------------------------
// K3: fused softmax + p_gen mix + scatter + log (row in SMEM)
// ---------------------------------------------------------------------------
__global__ void finalize_kernel(float* __restrict__ out,
                                const float* __restrict__ attn,
                                const void* __restrict__ ids_raw) {
    extern __shared__ float row[];
    __shared__ float red[32];
    __shared__ float s_bcast;

    const int b = blockIdx.x;
    const int tid = threadIdx.x;   // 1024
    float* o = out + (size_t)b * NV;

    float m = -INFINITY;
    for (int v = tid; v < NV; v += 1024) {
        float t = o[v];
        row[v] = t;
        m = fmaxf(m, t);
    }
    m = warp_reduce_max(m);
    if ((tid & 31) == 0) red[tid >> 5] = m;
    __syncthreads();
    if (tid < 32) {
        float t = warp_reduce_max(red[tid]);
        if (tid == 0) s_bcast = t;
    }
    __syncthreads();
    m = s_bcast;

    float sum = 0.f;
    for (int v = tid; v < NV; v += 1024) sum += __expf(row[v] - m);
    sum = warp_reduce_sum(sum);
    __syncthreads();
    if ((tid & 31) == 0) red[tid >> 5] = sum;
    __syncthreads();
    if (tid < 32) {
        float t = warp_reduce_sum(red[tid]);
        if (tid == 0) s_bcast = t;
    }
    __syncthreads();
    sum = s_bcast;

    const float pg = g_pgen[b];
    const float scale = pg / sum;

    for (int v = tid; v < NV; v += 1024) row[v] = __expf(row[v] - m) * scale;
    __syncthreads();

    if (tid < NS) {
        int id;
        if (g_ids_is64)
            id = (int)reinterpret_cast<const long long*>(ids_raw)[(size_t)b * NS + tid];
        else
            id = reinterpret_cast<const int*>(ids_raw)[(size_t)b * NS + tid];
        atomicAdd(&row[id], (1.f - pg) * attn[b * NS + tid]);
    }
    __syncthreads();

    for (int v = tid; v < NV; v += 1024) o[v] = logf(row[v] + 1e-40f);
}

// ---------------------------------------------------------------------------
// Launch
// ---------------------------------------------------------------------------
extern "C" void kernel_launch(void* const* d_in, const int* in_sizes, int n_in,
                              void* d_out, int out_size) {
    const float* x      = (const float*)d_in[0];
    const float* embed  = (const float*)d_in[1];
    const float* hidden = (const float*)d_in[2];
    const float* enc    = (const float*)d_in[3];
    const float* attn   = (const float*)d_in[4];
    const void*  ids    = d_in[5];
    const float* proj_w = (const float*)d_in[6];
    const float* proj_b = (const float*)d_in[7];
    const float* pgen_w = (const float*)d_in[8];
    const float* pgen_b = (const float*)d_in[9];
    float* out = (float*)d_out;

    detect_ids_kernel<<<1, 256>>>((const int*)ids);

    dim3 gctx(NB, SCHUNKS);
    ctx_partial_kernel<<<gctx, 256>>>(attn, enc, pgen_w);
    pgen_kernel<<<NB, 256>>>(hidden, embed, pgen_w, pgen_b);

    cudaFuncSetAttribute(gemm_mma_kernel,
                         cudaFuncAttributeMaxDynamicSharedMemorySize, GSMEM);
    dim3 gg(NB / BM, (NV + BN - 1) / BN);   // (2, 393): M-halves adjacent -> L2 reuse of W
    gemm_mma_kernel<<<gg, 256, GSMEM>>>(x, proj_w, proj_b, out);

    const int smem_bytes = NV * sizeof(float);
    cudaFuncSetAttribute(finalize_kernel,
                         cudaFuncAttributeMaxDynamicSharedMemorySize, smem_bytes);
    finalize_kernel<<<NB, 1024, smem_bytes>>>(out, attn, ids);
}

// round 9
// speedup vs baseline: 2.6635x; 1.1617x over previous
#include <cuda_runtime.h>
#include <cuda_bf16.h>
#include <math.h>

// Problem constants
static constexpr int NB   = 256;
static constexpr int NS   = 512;
static constexpr int NH   = 512;
static constexpr int NE   = 512;
static constexpr int NV   = 50257;
static constexpr int NENC = 1024;   // 2*H

static constexpr int SCHUNKS = 8;

// Scratch
__device__ float g_pgen[NB];
__device__ float g_dotp[SCHUNKS * NB];
__device__ int   g_ids_is64;

// ---------------------------------------------------------------------------
// helpers
// ---------------------------------------------------------------------------
__device__ __forceinline__ unsigned smem_u32(const void* p) {
    unsigned a;
    asm("{ .reg .u64 t; cvta.to.shared.u64 t, %1; cvt.u32.u64 %0, t; }"
        : "=r"(a) : "l"(p));
    return a;
}
__device__ __forceinline__ float warp_reduce_max(float v) {
    #pragma unroll
    for (int o = 16; o > 0; o >>= 1) v = fmaxf(v, __shfl_xor_sync(0xffffffffu, v, o));
    return v;
}
__device__ __forceinline__ float warp_reduce_sum(float v) {
    #pragma unroll
    for (int o = 16; o > 0; o >>= 1) v += __shfl_xor_sync(0xffffffffu, v, o);
    return v;
}

__device__ __forceinline__ void ldsm_x4(unsigned* r, unsigned addr) {
    asm volatile("ldmatrix.sync.aligned.m8n8.x4.shared.b16 {%0,%1,%2,%3}, [%4];"
                 : "=r"(r[0]), "=r"(r[1]), "=r"(r[2]), "=r"(r[3]) : "r"(addr));
}
__device__ __forceinline__ void mma_bf16(float* d, const unsigned* a, const unsigned* b) {
    asm volatile(
        "mma.sync.aligned.m16n8k16.row.col.f32.bf16.bf16.f32 "
        "{%0,%1,%2,%3}, {%4,%5,%6,%7}, {%8,%9}, {%0,%1,%2,%3};"
        : "+f"(d[0]), "+f"(d[1]), "+f"(d[2]), "+f"(d[3])
        : "r"(a[0]), "r"(a[1]), "r"(a[2]), "r"(a[3]), "r"(b[0]), "r"(b[1]));
}

// fp32x4 -> bf16 hi/lo, store as uint2 pairs
__device__ __forceinline__ void cvt_store_hilo(char* base, int hi_off, int lo_off,
                                               unsigned off, float4 w) {
    __nv_bfloat16 h0 = __float2bfloat16(w.x);
    __nv_bfloat16 h1 = __float2bfloat16(w.y);
    __nv_bfloat16 h2 = __float2bfloat16(w.z);
    __nv_bfloat16 h3 = __float2bfloat16(w.w);
    __nv_bfloat16 l0 = __float2bfloat16(w.x - __bfloat162float(h0));
    __nv_bfloat16 l1 = __float2bfloat16(w.y - __bfloat162float(h1));
    __nv_bfloat16 l2 = __float2bfloat16(w.z - __bfloat162float(h2));
    __nv_bfloat16 l3 = __float2bfloat16(w.w - __bfloat162float(h3));
    uint2 hv, lv;
    hv.x = (unsigned)__bfloat16_as_ushort(h0) | ((unsigned)__bfloat16_as_ushort(h1) << 16);
    hv.y = (unsigned)__bfloat16_as_ushort(h2) | ((unsigned)__bfloat16_as_ushort(h3) << 16);
    lv.x = (unsigned)__bfloat16_as_ushort(l0) | ((unsigned)__bfloat16_as_ushort(l1) << 16);
    lv.y = (unsigned)__bfloat16_as_ushort(l2) | ((unsigned)__bfloat16_as_ushort(l3) << 16);
    *reinterpret_cast<uint2*>(base + hi_off + off) = hv;
    *reinterpret_cast<uint2*>(base + lo_off + off) = lv;
}

// ---------------------------------------------------------------------------
// K0: int64-vs-int32 probe for input_ids
// ---------------------------------------------------------------------------
__global__ void detect_ids_kernel(const int* __restrict__ ids32) {
    int tid = threadIdx.x;
    int nz = 0;
    for (int i = tid; i < 4096; i += 256)
        nz |= (ids32[2 * i + 1] != 0);
    nz = __syncthreads_or(nz);
    if (tid == 0) g_ids_is64 = nz ? 0 : 1;
}

// ---------------------------------------------------------------------------
// K1a: partial context dot for p_gen (streams 537 MB)
// ---------------------------------------------------------------------------
__global__ void ctx_partial_kernel(const float* __restrict__ attn,
                                   const float* __restrict__ enc,
                                   const float* __restrict__ pgen_w) {
    const int b = blockIdx.x;
    const int chunk = blockIdx.y;
    const int tid = threadIdx.x;
    const int s0 = chunk * (NS / SCHUNKS);
    __shared__ float s_attn[NS / SCHUNKS];
    __shared__ float red[8];

    for (int i = tid; i < NS / SCHUNKS; i += 256) s_attn[i] = attn[b * NS + s0 + i];
    __syncthreads();

    float4 acc = make_float4(0.f, 0.f, 0.f, 0.f);
    #pragma unroll 4
    for (int s = 0; s < NS / SCHUNKS; s++) {
        const float a = s_attn[s];
        const float4 e = reinterpret_cast<const float4*>(
            enc + ((size_t)(s0 + s) * NB + b) * NENC)[tid];
        acc.x += a * e.x; acc.y += a * e.y; acc.z += a * e.z; acc.w += a * e.w;
    }
    const float* pwc = pgen_w + NH + NE + 4 * tid;
    float dot = acc.x * pwc[0] + acc.y * pwc[1] + acc.z * pwc[2] + acc.w * pwc[3];
    dot = warp_reduce_sum(dot);
    if ((tid & 31) == 0) red[tid >> 5] = dot;
    __syncthreads();
    if (tid == 0) {
        float t = 0.f;
        #pragma unroll
        for (int i = 0; i < 8; i++) t += red[i];
        g_dotp[chunk * NB + b] = t;
    }
}

// ---------------------------------------------------------------------------
// K1b: p_gen
// ---------------------------------------------------------------------------
__global__ void pgen_kernel(const float* __restrict__ hidden,
                            const float* __restrict__ embed,
                            const float* __restrict__ pgen_w,
                            const float* __restrict__ pgen_b) {
    const int b = blockIdx.x;
    const int tid = threadIdx.x;
    __shared__ float red[8];
    const int i0 = 2 * tid;
    float dot = hidden[b * NH + i0]     * pgen_w[i0]
              + hidden[b * NH + i0 + 1] * pgen_w[i0 + 1]
              + embed[b * NE + i0]      * pgen_w[NH + i0]
              + embed[b * NE + i0 + 1]  * pgen_w[NH + i0 + 1];
    dot = warp_reduce_sum(dot);
    if ((tid & 31) == 0) red[tid >> 5] = dot;
    __syncthreads();
    if (tid == 0) {
        float t = 0.f;
        #pragma unroll
        for (int i = 0; i < 8; i++) t += red[i];
        #pragma unroll
        for (int c = 0; c < SCHUNKS; c++) t += g_dotp[c * NB + b];
        t += pgen_b[0];
        g_pgen[b] = 1.f / (1.f + __expf(-t));
    }
}

// ---------------------------------------------------------------------------
// K2: logits via mma.sync bf16 hi/lo-split GEMM.
// CTA tile 128(M)x128(N)x32(K), 8 warps (2Mx4N), warp tile 64x32.
// Smem rows padded to 80B -> conflict-free ldmatrix. Double-buffered.
// __launch_bounds__(256,2): cap regs at 128 so 2 CTAs/SM cover each other's
// barrier + LDG stalls.
// ---------------------------------------------------------------------------
static constexpr int BM = 128, BN = 128, BK = 32;
static constexpr int TSTR = 80;             // bytes per 32-bf16 row (64B data + 16B pad)
static constexpr int TILE = BM * TSTR;      // 10240 B
static constexpr int BUF  = 4 * TILE;       // Ahi,Alo,Bhi,Blo
static constexpr int GSMEM = 2 * BUF;       // 81920 B

__global__ __launch_bounds__(256, 2)
void gemm_mma_kernel(const float* __restrict__ X,     // [B, H]
                     const float* __restrict__ W,     // [V, H]
                     const float* __restrict__ bias,  // [V]
                     float* __restrict__ out) {       // [B, V]
    extern __shared__ char sm[];
    __shared__ float s_bias[BN];
    const unsigned smb = smem_u32(sm);
    const int tid  = threadIdx.x;
    const int lane = tid & 31;
    const int wid  = tid >> 5;
    const int m_base = blockIdx.x * BM;     // 0 or 128
    const int n_base = blockIdx.y * BN;
    const int wm = (wid >> 2) * 64;
    const int wn = (wid & 3) * 32;

    float acc[4][4][4] = {};
    float4 stA[4], stB[4];

    // gmem load of one K-chunk into staging regs
    auto ldg = [&](int k0) {
        #pragma unroll
        for (int i = 0; i < 4; i++) {
            int idx = i * 256 + tid;
            int r = idx >> 3, c = idx & 7;
            stA[i] = *reinterpret_cast<const float4*>(X + (size_t)(m_base + r) * NH + k0 + c * 4);
            int v = n_base + r;
            stB[i] = (v < NV)
                ? *reinterpret_cast<const float4*>(W + (size_t)v * NH + k0 + c * 4)
                : make_float4(0.f, 0.f, 0.f, 0.f);
        }
    };
    // convert + store staging regs into smem buffer bsel
    auto sts = [&](int bsel) {
        char* base = sm + bsel * BUF;
        #pragma unroll
        for (int i = 0; i < 4; i++) {
            int idx = i * 256 + tid;
            int r = idx >> 3, c = idx & 7;
            unsigned off = r * TSTR + c * 8;
            cvt_store_hilo(base, 0,        TILE,     off, stA[i]);
            cvt_store_hilo(base, 2 * TILE, 3 * TILE, off, stB[i]);
        }
    };
    auto compute = [&](int bsel) {
        const unsigned Ah = smb + bsel * BUF;
        const unsigned Bh = Ah + 2 * TILE;
        const int arow = wm + (lane & 15);
        const int nrow = wn + (lane & 7) + ((lane & 16) ? 8 : 0);
        #pragma unroll
        for (int kk = 0; kk < BK; kk += 16) {
            const unsigned akb = (kk + ((lane & 16) ? 8 : 0)) * 2;
            const unsigned bkb = (kk + ((lane & 8)  ? 8 : 0)) * 2;
            unsigned ah[4][4], al[4][4], bh[4][2], bl[4][2];
            #pragma unroll
            for (int mt = 0; mt < 4; mt++) {
                unsigned ad = Ah + (unsigned)(arow + mt * 16) * TSTR + akb;
                ldsm_x4(ah[mt], ad);
                ldsm_x4(al[mt], ad + TILE);
            }
            #pragma unroll
            for (int jp = 0; jp < 2; jp++) {
                unsigned bd = Bh + (unsigned)(nrow + jp * 16) * TSTR + bkb;
                unsigned r[4];
                ldsm_x4(r, bd);
                bh[jp * 2][0] = r[0]; bh[jp * 2][1] = r[1];
                bh[jp * 2 + 1][0] = r[2]; bh[jp * 2 + 1][1] = r[3];
                ldsm_x4(r, bd + TILE);
                bl[jp * 2][0] = r[0]; bl[jp * 2][1] = r[1];
                bl[jp * 2 + 1][0] = r[2]; bl[jp * 2 + 1][1] = r[3];
            }
            #pragma unroll
            for (int mt = 0; mt < 4; mt++)
                #pragma unroll
                for (int nt = 0; nt < 4; nt++) {
                    mma_bf16(acc[mt][nt], ah[mt], bh[nt]);
                    mma_bf16(acc[mt][nt], ah[mt], bl[nt]);
                    mma_bf16(acc[mt][nt], al[mt], bh[nt]);
                }
        }
    };

    ldg(0);
    sts(0);
    __syncthreads();
    #pragma unroll 1
    for (int ck = 1; ck <= NH / BK; ck++) {
        if (ck < NH / BK) ldg(ck * BK);
        compute((ck - 1) & 1);
        if (ck < NH / BK) sts(ck & 1);
        __syncthreads();
    }

    // epilogue
    for (int i = tid; i < BN; i += 256) {
        int v = n_base + i;
        s_bias[i] = (v < NV) ? bias[v] : 0.f;
    }
    __syncthreads();

    const int g  = lane >> 2;
    const int t2 = (lane & 3) * 2;
    #pragma unroll
    for (int mt = 0; mt < 4; mt++) {
        const int m0 = m_base + wm + mt * 16 + g;
        float* row0 = out + (size_t)m0 * NV;
        float* row1 = out + (size_t)(m0 + 8) * NV;
        #pragma unroll
        for (int nt = 0; nt < 4; nt++) {
            const int ncol = wn + nt * 8 + t2;
            const int v = n_base + ncol;
            if (v < NV) {
                const float b0 = s_bias[ncol];
                row0[v] = acc[mt][nt][0] + b0;
                row1[v] = acc[mt][nt][2] + b0;
                if (v + 1 < NV) {
                    const float b1 = s_bias[ncol + 1];
                    row0[v + 1] = acc[mt][nt][1] + b1;
                    row1[v + 1] = acc[mt][nt][3] + b1;
                }
            }
        }
    }
}

// ---------------------------------------------------------------------------
// K3: fused softmax + p_gen mix + scatter + log (row in SMEM).
// exp computed once (cached in smem during the sum pass).
// ---------------------------------------------------------------------------
__global__ void finalize_kernel(float* __restrict__ out,
                                const float* __restrict__ attn,
                                const void* __restrict__ ids_raw) {
    extern __shared__ float row[];
    __shared__ float red[32];
    __shared__ float s_bcast;

    const int b = blockIdx.x;
    const int tid = threadIdx.x;   // 1024
    float* o = out + (size_t)b * NV;

    float m = -INFINITY;
    for (int v = tid; v < NV; v += 1024) {
        float t = o[v];
        row[v] = t;
        m = fmaxf(m, t);
    }
    m = warp_reduce_max(m);
    if ((tid & 31) == 0) red[tid >> 5] = m;
    __syncthreads();
    if (tid < 32) {
        float t = warp_reduce_max(red[tid]);
        if (tid == 0) s_bcast = t;
    }
    __syncthreads();
    m = s_bcast;

    // sum pass: write exp back into smem (no recompute later)
    float sum = 0.f;
    for (int v = tid; v < NV; v += 1024) {
        float e = __expf(row[v] - m);
        row[v] = e;
        sum += e;
    }
    sum = warp_reduce_sum(sum);
    __syncthreads();
    if ((tid & 31) == 0) red[tid >> 5] = sum;
    __syncthreads();
    if (tid < 32) {
        float t = warp_reduce_sum(red[tid]);
        if (tid == 0) s_bcast = t;
    }
    __syncthreads();
    sum = s_bcast;

    const float pg = g_pgen[b];
    const float scale = pg / sum;

    for (int v = tid; v < NV; v += 1024) row[v] *= scale;
    __syncthreads();

    if (tid < NS) {
        int id;
        if (g_ids_is64)
            id = (int)reinterpret_cast<const long long*>(ids_raw)[(size_t)b * NS + tid];
        else
            id = reinterpret_cast<const int*>(ids_raw)[(size_t)b * NS + tid];
        atomicAdd(&row[id], (1.f - pg) * attn[b * NS + tid]);
    }
    __syncthreads();

    for (int v = tid; v < NV; v += 1024) o[v] = logf(row[v] + 1e-40f);
}

// ---------------------------------------------------------------------------
// Launch
// ---------------------------------------------------------------------------
extern "C" void kernel_launch(void* const* d_in, const int* in_sizes, int n_in,
                              void* d_out, int out_size) {
    const float* x      = (const float*)d_in[0];
    const float* embed  = (const float*)d_in[1];
    const float* hidden = (const float*)d_in[2];
    const float* enc    = (const float*)d_in[3];
    const float* attn   = (const float*)d_in[4];
    const void*  ids    = d_in[5];
    const float* proj_w = (const float*)d_in[6];
    const float* proj_b = (const float*)d_in[7];
    const float* pgen_w = (const float*)d_in[8];
    const float* pgen_b = (const float*)d_in[9];
    float* out = (float*)d_out;

    detect_ids_kernel<<<1, 256>>>((const int*)ids);

    dim3 gctx(NB, SCHUNKS);
    ctx_partial_kernel<<<gctx, 256>>>(attn, enc, pgen_w);
    pgen_kernel<<<NB, 256>>>(hidden, embed, pgen_w, pgen_b);

    cudaFuncSetAttribute(gemm_mma_kernel,
                         cudaFuncAttributeMaxDynamicSharedMemorySize, GSMEM);
    dim3 gg(NB / BM, (NV + BN - 1) / BN);   // (2, 393): M-halves adjacent -> L2 reuse of W
    gemm_mma_kernel<<<gg, 256, GSMEM>>>(x, proj_w, proj_b, out);

    const int smem_bytes = NV * sizeof(float);
    cudaFuncSetAttribute(finalize_kernel,
                         cudaFuncAttributeMaxDynamicSharedMemorySize, smem_bytes);
    finalize_kernel<<<NB, 1024, smem_bytes>>>(out, attn, ids);
}

// round 10
// speedup vs baseline: 3.5834x; 1.3454x over previous
#include <cuda_runtime.h>
#include <cuda_fp16.h>
#include <math.h>

// Problem constants
static constexpr int NB   = 256;
static constexpr int NS   = 512;
static constexpr int NH   = 512;
static constexpr int NE   = 512;
static constexpr int NV   = 50257;
static constexpr int NENC = 1024;   // 2*H

static constexpr int SCHUNKS = 8;

// Scratch
__device__ float g_pgen[NB];
__device__ float g_dotp[SCHUNKS * NB];
__device__ int   g_ids_is64;

// ---------------------------------------------------------------------------
// helpers
// ---------------------------------------------------------------------------
__device__ __forceinline__ unsigned smem_u32(const void* p) {
    unsigned a;
    asm("{ .reg .u64 t; cvta.to.shared.u64 t, %1; cvt.u32.u64 %0, t; }"
        : "=r"(a) : "l"(p));
    return a;
}
__device__ __forceinline__ float warp_reduce_max(float v) {
    #pragma unroll
    for (int o = 16; o > 0; o >>= 1) v = fmaxf(v, __shfl_xor_sync(0xffffffffu, v, o));
    return v;
}
__device__ __forceinline__ float warp_reduce_sum(float v) {
    #pragma unroll
    for (int o = 16; o > 0; o >>= 1) v += __shfl_xor_sync(0xffffffffu, v, o);
    return v;
}

__device__ __forceinline__ void ldsm_x4(unsigned* r, unsigned addr) {
    asm volatile("ldmatrix.sync.aligned.m8n8.x4.shared.b16 {%0,%1,%2,%3}, [%4];"
                 : "=r"(r[0]), "=r"(r[1]), "=r"(r[2]), "=r"(r[3]) : "r"(addr));
}
__device__ __forceinline__ void mma_f16(float* d, const unsigned* a, const unsigned* b) {
    asm volatile(
        "mma.sync.aligned.m16n8k16.row.col.f32.f16.f16.f32 "
        "{%0,%1,%2,%3}, {%4,%5,%6,%7}, {%8,%9}, {%0,%1,%2,%3};"
        : "+f"(d[0]), "+f"(d[1]), "+f"(d[2]), "+f"(d[3])
        : "r"(a[0]), "r"(a[1]), "r"(a[2]), "r"(a[3]), "r"(b[0]), "r"(b[1]));
}

// fp32x4 -> fp16x4, store as uint2
__device__ __forceinline__ void cvt_store_f16(char* base, unsigned off, float4 w) {
    __half2 p0 = __floats2half2_rn(w.x, w.y);
    __half2 p1 = __floats2half2_rn(w.z, w.w);
    uint2 v;
    v.x = *reinterpret_cast<unsigned*>(&p0);
    v.y = *reinterpret_cast<unsigned*>(&p1);
    *reinterpret_cast<uint2*>(base + off) = v;
}

// ---------------------------------------------------------------------------
// K0: int64-vs-int32 probe for input_ids
// ---------------------------------------------------------------------------
__global__ void detect_ids_kernel(const int* __restrict__ ids32) {
    int tid = threadIdx.x;
    int nz = 0;
    for (int i = tid; i < 4096; i += 256)
        nz |= (ids32[2 * i + 1] != 0);
    nz = __syncthreads_or(nz);
    if (tid == 0) g_ids_is64 = nz ? 0 : 1;
}

// ---------------------------------------------------------------------------
// K1a: partial context dot for p_gen (streams 537 MB)
// ---------------------------------------------------------------------------
__global__ void ctx_partial_kernel(const float* __restrict__ attn,
                                   const float* __restrict__ enc,
                                   const float* __restrict__ pgen_w) {
    const int b = blockIdx.x;
    const int chunk = blockIdx.y;
    const int tid = threadIdx.x;
    const int s0 = chunk * (NS / SCHUNKS);
    __shared__ float s_attn[NS / SCHUNKS];
    __shared__ float red[8];

    for (int i = tid; i < NS / SCHUNKS; i += 256) s_attn[i] = attn[b * NS + s0 + i];
    __syncthreads();

    float4 acc = make_float4(0.f, 0.f, 0.f, 0.f);
    #pragma unroll 4
    for (int s = 0; s < NS / SCHUNKS; s++) {
        const float a = s_attn[s];
        const float4 e = reinterpret_cast<const float4*>(
            enc + ((size_t)(s0 + s) * NB + b) * NENC)[tid];
        acc.x += a * e.x; acc.y += a * e.y; acc.z += a * e.z; acc.w += a * e.w;
    }
    const float* pwc = pgen_w + NH + NE + 4 * tid;
    float dot = acc.x * pwc[0] + acc.y * pwc[1] + acc.z * pwc[2] + acc.w * pwc[3];
    dot = warp_reduce_sum(dot);
    if ((tid & 31) == 0) red[tid >> 5] = dot;
    __syncthreads();
    if (tid == 0) {
        float t = 0.f;
        #pragma unroll
        for (int i = 0; i < 8; i++) t += red[i];
        g_dotp[chunk * NB + b] = t;
    }
}

// ---------------------------------------------------------------------------
// K1b: p_gen
// ---------------------------------------------------------------------------
__global__ void pgen_kernel(const float* __restrict__ hidden,
                            const float* __restrict__ embed,
                            const float* __restrict__ pgen_w,
                            const float* __restrict__ pgen_b) {
    const int b = blockIdx.x;
    const int tid = threadIdx.x;
    __shared__ float red[8];
    const int i0 = 2 * tid;
    float dot = hidden[b * NH + i0]     * pgen_w[i0]
              + hidden[b * NH + i0 + 1] * pgen_w[i0 + 1]
              + embed[b * NE + i0]      * pgen_w[NH + i0]
              + embed[b * NE + i0 + 1]  * pgen_w[NH + i0 + 1];
    dot = warp_reduce_sum(dot);
    if ((tid & 31) == 0) red[tid >> 5] = dot;
    __syncthreads();
    if (tid == 0) {
        float t = 0.f;
        #pragma unroll
        for (int i = 0; i < 8; i++) t += red[i];
        #pragma unroll
        for (int c = 0; c < SCHUNKS; c++) t += g_dotp[c * NB + b];
        t += pgen_b[0];
        g_pgen[b] = 1.f / (1.f + __expf(-t));
    }
}

// ---------------------------------------------------------------------------
// K2: logits via mma.sync fp16 GEMM (single term; ~5e-4 logit rms error,
// far under the 1e-3 gate after log-softmax).
// CTA tile 128(M)x128(N)x32(K), 8 warps (2Mx4N), warp tile 64x32.
// Smem rows padded to 80B -> conflict-free ldmatrix. Double-buffered.
// ---------------------------------------------------------------------------
static constexpr int BM = 128, BN = 128, BK = 32;
static constexpr int TSTR = 80;             // bytes per 32-f16 row (64B data + 16B pad)
static constexpr int TILE = BM * TSTR;      // 10240 B
static constexpr int BUF  = 2 * TILE;       // A, B
static constexpr int GSMEM = 2 * BUF;       // 40960 B

__global__ __launch_bounds__(256, 2)
void gemm_mma_kernel(const float* __restrict__ X,     // [B, H]
                     const float* __restrict__ W,     // [V, H]
                     const float* __restrict__ bias,  // [V]
                     float* __restrict__ out) {       // [B, V]
    extern __shared__ char sm[];
    __shared__ float s_bias[BN];
    const unsigned smb = smem_u32(sm);
    const int tid  = threadIdx.x;
    const int lane = tid & 31;
    const int wid  = tid >> 5;
    const int m_base = blockIdx.x * BM;     // 0 or 128
    const int n_base = blockIdx.y * BN;
    const int wm = (wid >> 2) * 64;
    const int wn = (wid & 3) * 32;

    float acc[4][4][4] = {};
    float4 stA[4], stB[4];

    // gmem load of one K-chunk into staging regs
    auto ldg = [&](int k0) {
        #pragma unroll
        for (int i = 0; i < 4; i++) {
            int idx = i * 256 + tid;
            int r = idx >> 3, c = idx & 7;
            stA[i] = *reinterpret_cast<const float4*>(X + (size_t)(m_base + r) * NH + k0 + c * 4);
            int v = n_base + r;
            stB[i] = (v < NV)
                ? *reinterpret_cast<const float4*>(W + (size_t)v * NH + k0 + c * 4)
                : make_float4(0.f, 0.f, 0.f, 0.f);
        }
    };
    // convert + store staging regs into smem buffer bsel
    auto sts = [&](int bsel) {
        char* base = sm + bsel * BUF;
        #pragma unroll
        for (int i = 0; i < 4; i++) {
            int idx = i * 256 + tid;
            int r = idx >> 3, c = idx & 7;
            unsigned off = r * TSTR + c * 8;
            cvt_store_f16(base, off, stA[i]);
            cvt_store_f16(base + TILE, off, stB[i]);
        }
    };
    auto compute = [&](int bsel) {
        const unsigned Ah = smb + bsel * BUF;
        const unsigned Bh = Ah + TILE;
        const int arow = wm + (lane & 15);
        const int nrow = wn + (lane & 7) + ((lane & 16) ? 8 : 0);
        #pragma unroll
        for (int kk = 0; kk < BK; kk += 16) {
            const unsigned akb = (kk + ((lane & 16) ? 8 : 0)) * 2;
            const unsigned bkb = (kk + ((lane & 8)  ? 8 : 0)) * 2;
            unsigned ah[4][4], bh[4][2];
            #pragma unroll
            for (int mt = 0; mt < 4; mt++) {
                unsigned ad = Ah + (unsigned)(arow + mt * 16) * TSTR + akb;
                ldsm_x4(ah[mt], ad);
            }
            #pragma unroll
            for (int jp = 0; jp < 2; jp++) {
                unsigned bd = Bh + (unsigned)(nrow + jp * 16) * TSTR + bkb;
                unsigned r[4];
                ldsm_x4(r, bd);
                bh[jp * 2][0] = r[0]; bh[jp * 2][1] = r[1];
                bh[jp * 2 + 1][0] = r[2]; bh[jp * 2 + 1][1] = r[3];
            }
            #pragma unroll
            for (int mt = 0; mt < 4; mt++)
                #pragma unroll
                for (int nt = 0; nt < 4; nt++)
                    mma_f16(acc[mt][nt], ah[mt], bh[nt]);
        }
    };

    ldg(0);
    sts(0);
    __syncthreads();
    #pragma unroll 1
    for (int ck = 1; ck <= NH / BK; ck++) {
        if (ck < NH / BK) ldg(ck * BK);
        compute((ck - 1) & 1);
        if (ck < NH / BK) sts(ck & 1);
        __syncthreads();
    }

    // epilogue
    for (int i = tid; i < BN; i += 256) {
        int v = n_base + i;
        s_bias[i] = (v < NV) ? bias[v] : 0.f;
    }
    __syncthreads();

    const int g  = lane >> 2;
    const int t2 = (lane & 3) * 2;
    #pragma unroll
    for (int mt = 0; mt < 4; mt++) {
        const int m0 = m_base + wm + mt * 16 + g;
        float* row0 = out + (size_t)m0 * NV;
        float* row1 = out + (size_t)(m0 + 8) * NV;
        #pragma unroll
        for (int nt = 0; nt < 4; nt++) {
            const int ncol = wn + nt * 8 + t2;
            const int v = n_base + ncol;
            if (v < NV) {
                const float b0 = s_bias[ncol];
                row0[v] = acc[mt][nt][0] + b0;
                row1[v] = acc[mt][nt][2] + b0;
                if (v + 1 < NV) {
                    const float b1 = s_bias[ncol + 1];
                    row0[v + 1] = acc[mt][nt][1] + b1;
                    row1[v + 1] = acc[mt][nt][3] + b1;
                }
            }
        }
    }
}

// ---------------------------------------------------------------------------
// K3: fused softmax + p_gen mix + scatter + log (row in SMEM).
// exp computed once (cached in smem during the sum pass).
// ---------------------------------------------------------------------------
__global__ void finalize_kernel(float* __restrict__ out,
                                const float* __restrict__ attn,
                                const void* __restrict__ ids_raw) {
    extern __shared__ float row[];
    __shared__ float red[32];
    __shared__ float s_bcast;

    const int b = blockIdx.x;
    const int tid = threadIdx.x;   // 1024
    float* o = out + (size_t)b * NV;

    float m = -INFINITY;
    for (int v = tid; v < NV; v += 1024) {
        float t = o[v];
        row[v] = t;
        m = fmaxf(m, t);
    }
    m = warp_reduce_max(m);
    if ((tid & 31) == 0) red[tid >> 5] = m;
    __syncthreads();
    if (tid < 32) {
        float t = warp_reduce_max(red[tid]);
        if (tid == 0) s_bcast = t;
    }
    __syncthreads();
    m = s_bcast;

    float sum = 0.f;
    for (int v = tid; v < NV; v += 1024) {
        float e = __expf(row[v] - m);
        row[v] = e;
        sum += e;
    }
    sum = warp_reduce_sum(sum);
    __syncthreads();
    if ((tid & 31) == 0) red[tid >> 5] = sum;
    __syncthreads();
    if (tid < 32) {
        float t = warp_reduce_sum(red[tid]);
        if (tid == 0) s_bcast = t;
    }
    __syncthreads();
    sum = s_bcast;

    const float pg = g_pgen[b];
    const float scale = pg / sum;

    for (int v = tid; v < NV; v += 1024) row[v] *= scale;
    __syncthreads();

    if (tid < NS) {
        int id;
        if (g_ids_is64)
            id = (int)reinterpret_cast<const long long*>(ids_raw)[(size_t)b * NS + tid];
        else
            id = reinterpret_cast<const int*>(ids_raw)[(size_t)b * NS + tid];
        atomicAdd(&row[id], (1.f - pg) * attn[b * NS + tid]);
    }
    __syncthreads();

    for (int v = tid; v < NV; v += 1024) o[v] = logf(row[v] + 1e-40f);
}

// ---------------------------------------------------------------------------
// Launch
// ---------------------------------------------------------------------------
extern "C" void kernel_launch(void* const* d_in, const int* in_sizes, int n_in,
                              void* d_out, int out_size) {
    const float* x      = (const float*)d_in[0];
    const float* embed  = (const float*)d_in[1];
    const float* hidden = (const float*)d_in[2];
    const float* enc    = (const float*)d_in[3];
    const float* attn   = (const float*)d_in[4];
    const void*  ids    = d_in[5];
    const float* proj_w = (const float*)d_in[6];
    const float* proj_b = (const float*)d_in[7];
    const float* pgen_w = (const float*)d_in[8];
    const float* pgen_b = (const float*)d_in[9];
    float* out = (float*)d_out;

    detect_ids_kernel<<<1, 256>>>((const int*)ids);

    dim3 gctx(NB, SCHUNKS);
    ctx_partial_kernel<<<gctx, 256>>>(attn, enc, pgen_w);
    pgen_kernel<<<NB, 256>>>(hidden, embed, pgen_w, pgen_b);

    cudaFuncSetAttribute(gemm_mma_kernel,
                         cudaFuncAttributeMaxDynamicSharedMemorySize, GSMEM);
    dim3 gg(NB / BM, (NV + BN - 1) / BN);   // (2, 393): M-halves adjacent -> L2 reuse of W
    gemm_mma_kernel<<<gg, 256, GSMEM>>>(x, proj_w, proj_b, out);

    const int smem_bytes = NV * sizeof(float);
    cudaFuncSetAttribute(finalize_kernel,
                         cudaFuncAttributeMaxDynamicSharedMemorySize, smem_bytes);
    finalize_kernel<<<NB, 1024, smem_bytes>>>(out, attn, ids);
}

// round 11
// speedup vs baseline: 3.5902x; 1.0019x over previous
#include <cuda_runtime.h>
#include <cuda_fp16.h>
#include <math.h>

// Problem constants
static constexpr int NB   = 256;
static constexpr int NS   = 512;
static constexpr int NH   = 512;
static constexpr int NE   = 512;
static constexpr int NV   = 50257;
static constexpr int NENC = 1024;   // 2*H

static constexpr int SCHUNKS = 8;

// Scratch
__device__ float g_pgen[NB];
__device__ float g_dotp[SCHUNKS * NB];
__device__ int   g_ids_is64;

// ---------------------------------------------------------------------------
// helpers
// ---------------------------------------------------------------------------
__device__ __forceinline__ unsigned smem_u32(const void* p) {
    unsigned a;
    asm("{ .reg .u64 t; cvta.to.shared.u64 t, %1; cvt.u32.u64 %0, t; }"
        : "=r"(a) : "l"(p));
    return a;
}
__device__ __forceinline__ float warp_reduce_max(float v) {
    #pragma unroll
    for (int o = 16; o > 0; o >>= 1) v = fmaxf(v, __shfl_xor_sync(0xffffffffu, v, o));
    return v;
}
__device__ __forceinline__ float warp_reduce_sum(float v) {
    #pragma unroll
    for (int o = 16; o > 0; o >>= 1) v += __shfl_xor_sync(0xffffffffu, v, o);
    return v;
}

__device__ __forceinline__ void ldsm_x4(unsigned* r, unsigned addr) {
    asm volatile("ldmatrix.sync.aligned.m8n8.x4.shared.b16 {%0,%1,%2,%3}, [%4];"
                 : "=r"(r[0]), "=r"(r[1]), "=r"(r[2]), "=r"(r[3]) : "r"(addr));
}
__device__ __forceinline__ void mma_f16(float* d, const unsigned* a, const unsigned* b) {
    asm volatile(
        "mma.sync.aligned.m16n8k16.row.col.f32.f16.f16.f32 "
        "{%0,%1,%2,%3}, {%4,%5,%6,%7}, {%8,%9}, {%0,%1,%2,%3};"
        : "+f"(d[0]), "+f"(d[1]), "+f"(d[2]), "+f"(d[3])
        : "r"(a[0]), "r"(a[1]), "r"(a[2]), "r"(a[3]), "r"(b[0]), "r"(b[1]));
}

// fp32x4 -> fp16x4, store as uint2
__device__ __forceinline__ void cvt_store_f16(char* base, unsigned off, float4 w) {
    __half2 p0 = __floats2half2_rn(w.x, w.y);
    __half2 p1 = __floats2half2_rn(w.z, w.w);
    uint2 v;
    v.x = *reinterpret_cast<unsigned*>(&p0);
    v.y = *reinterpret_cast<unsigned*>(&p1);
    *reinterpret_cast<uint2*>(base + off) = v;
}

// ---------------------------------------------------------------------------
// K0: int64-vs-int32 probe for input_ids
// ---------------------------------------------------------------------------
__global__ void detect_ids_kernel(const int* __restrict__ ids32) {
    int tid = threadIdx.x;
    int nz = 0;
    for (int i = tid; i < 4096; i += 256)
        nz |= (ids32[2 * i + 1] != 0);
    nz = __syncthreads_or(nz);
    if (tid == 0) g_ids_is64 = nz ? 0 : 1;
}

// ---------------------------------------------------------------------------
// K1a: partial context dot for p_gen (streams 537 MB)
// ---------------------------------------------------------------------------
__global__ void ctx_partial_kernel(const float* __restrict__ attn,
                                   const float* __restrict__ enc,
                                   const float* __restrict__ pgen_w) {
    const int b = blockIdx.x;
    const int chunk = blockIdx.y;
    const int tid = threadIdx.x;
    const int s0 = chunk * (NS / SCHUNKS);
    __shared__ float s_attn[NS / SCHUNKS];
    __shared__ float red[8];

    for (int i = tid; i < NS / SCHUNKS; i += 256) s_attn[i] = attn[b * NS + s0 + i];
    __syncthreads();

    float4 acc = make_float4(0.f, 0.f, 0.f, 0.f);
    #pragma unroll 4
    for (int s = 0; s < NS / SCHUNKS; s++) {
        const float a = s_attn[s];
        const float4 e = reinterpret_cast<const float4*>(
            enc + ((size_t)(s0 + s) * NB + b) * NENC)[tid];
        acc.x += a * e.x; acc.y += a * e.y; acc.z += a * e.z; acc.w += a * e.w;
    }
    const float* pwc = pgen_w + NH + NE + 4 * tid;
    float dot = acc.x * pwc[0] + acc.y * pwc[1] + acc.z * pwc[2] + acc.w * pwc[3];
    dot = warp_reduce_sum(dot);
    if ((tid & 31) == 0) red[tid >> 5] = dot;
    __syncthreads();
    if (tid == 0) {
        float t = 0.f;
        #pragma unroll
        for (int i = 0; i < 8; i++) t += red[i];
        g_dotp[chunk * NB + b] = t;
    }
}

// ---------------------------------------------------------------------------
// K1b: p_gen
// ---------------------------------------------------------------------------
__global__ void pgen_kernel(const float* __restrict__ hidden,
                            const float* __restrict__ embed,
                            const float* __restrict__ pgen_w,
                            const float* __restrict__ pgen_b) {
    const int b = blockIdx.x;
    const int tid = threadIdx.x;
    __shared__ float red[8];
    const int i0 = 2 * tid;
    float dot = hidden[b * NH + i0]     * pgen_w[i0]
              + hidden[b * NH + i0 + 1] * pgen_w[i0 + 1]
              + embed[b * NE + i0]      * pgen_w[NH + i0]
              + embed[b * NE + i0 + 1]  * pgen_w[NH + i0 + 1];
    dot = warp_reduce_sum(dot);
    if ((tid & 31) == 0) red[tid >> 5] = dot;
    __syncthreads();
    if (tid == 0) {
        float t = 0.f;
        #pragma unroll
        for (int i = 0; i < 8; i++) t += red[i];
        #pragma unroll
        for (int c = 0; c < SCHUNKS; c++) t += g_dotp[c * NB + b];
        t += pgen_b[0];
        g_pgen[b] = 1.f / (1.f + __expf(-t));
    }
}

// ---------------------------------------------------------------------------
// K2: logits via mma.sync fp16 GEMM (single term; ~5e-4 logit rms error,
// far under the 1e-3 gate after log-softmax).
// CTA tile 128(M)x128(N)x32(K), 8 warps (2Mx4N), warp tile 64x32.
// Smem rows padded to 80B -> conflict-free ldmatrix. Double-buffered.
// ---------------------------------------------------------------------------
static constexpr int BM = 128, BN = 128, BK = 32;
static constexpr int TSTR = 80;             // bytes per 32-f16 row (64B data + 16B pad)
static constexpr int TILE = BM * TSTR;      // 10240 B
static constexpr int BUF  = 2 * TILE;       // A, B
static constexpr int GSMEM = 2 * BUF;       // 40960 B

__global__ __launch_bounds__(256, 2)
void gemm_mma_kernel(const float* __restrict__ X,     // [B, H]
                     const float* __restrict__ W,     // [V, H]
                     const float* __restrict__ bias,  // [V]
                     float* __restrict__ out) {       // [B, V]
    extern __shared__ char sm[];
    __shared__ float s_bias[BN];
    const unsigned smb = smem_u32(sm);
    const int tid  = threadIdx.x;
    const int lane = tid & 31;
    const int wid  = tid >> 5;
    const int m_base = blockIdx.x * BM;     // 0 or 128
    const int n_base = blockIdx.y * BN;
    const int wm = (wid >> 2) * 64;
    const int wn = (wid & 3) * 32;

    float acc[4][4][4] = {};
    float4 stA[4], stB[4];

    // gmem load of one K-chunk into staging regs
    auto ldg = [&](int k0) {
        #pragma unroll
        for (int i = 0; i < 4; i++) {
            int idx = i * 256 + tid;
            int r = idx >> 3, c = idx & 7;
            stA[i] = *reinterpret_cast<const float4*>(X + (size_t)(m_base + r) * NH + k0 + c * 4);
            int v = n_base + r;
            stB[i] = (v < NV)
                ? *reinterpret_cast<const float4*>(W + (size_t)v * NH + k0 + c * 4)
                : make_float4(0.f, 0.f, 0.f, 0.f);
        }
    };
    // convert + store staging regs into smem buffer bsel
    auto sts = [&](int bsel) {
        char* base = sm + bsel * BUF;
        #pragma unroll
        for (int i = 0; i < 4; i++) {
            int idx = i * 256 + tid;
            int r = idx >> 3, c = idx & 7;
            unsigned off = r * TSTR + c * 8;
            cvt_store_f16(base, off, stA[i]);
            cvt_store_f16(base + TILE, off, stB[i]);
        }
    };
    auto compute = [&](int bsel) {
        const unsigned Ah = smb + bsel * BUF;
        const unsigned Bh = Ah + TILE;
        const int arow = wm + (lane & 15);
        const int nrow = wn + (lane & 7) + ((lane & 16) ? 8 : 0);
        #pragma unroll
        for (int kk = 0; kk < BK; kk += 16) {
            const unsigned akb = (kk + ((lane & 16) ? 8 : 0)) * 2;
            const unsigned bkb = (kk + ((lane & 8)  ? 8 : 0)) * 2;
            unsigned ah[4][4], bh[4][2];
            #pragma unroll
            for (int mt = 0; mt < 4; mt++) {
                unsigned ad = Ah + (unsigned)(arow + mt * 16) * TSTR + akb;
                ldsm_x4(ah[mt], ad);
            }
            #pragma unroll
            for (int jp = 0; jp < 2; jp++) {
                unsigned bd = Bh + (unsigned)(nrow + jp * 16) * TSTR + bkb;
                unsigned r[4];
                ldsm_x4(r, bd);
                bh[jp * 2][0] = r[0]; bh[jp * 2][1] = r[1];
                bh[jp * 2 + 1][0] = r[2]; bh[jp * 2 + 1][1] = r[3];
            }
            #pragma unroll
            for (int mt = 0; mt < 4; mt++)
                #pragma unroll
                for (int nt = 0; nt < 4; nt++)
                    mma_f16(acc[mt][nt], ah[mt], bh[nt]);
        }
    };

    ldg(0);
    sts(0);
    __syncthreads();
    #pragma unroll 1
    for (int ck = 1; ck <= NH / BK; ck++) {
        if (ck < NH / BK) ldg(ck * BK);
        compute((ck - 1) & 1);
        if (ck < NH / BK) sts(ck & 1);
        __syncthreads();
    }

    // epilogue
    for (int i = tid; i < BN; i += 256) {
        int v = n_base + i;
        s_bias[i] = (v < NV) ? bias[v] : 0.f;
    }
    __syncthreads();

    const int g  = lane >> 2;
    const int t2 = (lane & 3) * 2;
    #pragma unroll
    for (int mt = 0; mt < 4; mt++) {
        const int m0 = m_base + wm + mt * 16 + g;
        float* row0 = out + (size_t)m0 * NV;
        float* row1 = out + (size_t)(m0 + 8) * NV;
        #pragma unroll
        for (int nt = 0; nt < 4; nt++) {
            const int ncol = wn + nt * 8 + t2;
            const int v = n_base + ncol;
            if (v < NV) {
                const float b0 = s_bias[ncol];
                row0[v] = acc[mt][nt][0] + b0;
                row1[v] = acc[mt][nt][2] + b0;
                if (v + 1 < NV) {
                    const float b1 = s_bias[ncol + 1];
                    row0[v + 1] = acc[mt][nt][1] + b1;
                    row1[v + 1] = acc[mt][nt][3] + b1;
                }
            }
        }
    }
}

// ---------------------------------------------------------------------------
// K3: fused softmax + p_gen mix + scatter + log (row in SMEM).
// exp computed once (cached in smem during the sum pass).
// ---------------------------------------------------------------------------
__global__ void finalize_kernel(float* __restrict__ out,
                                const float* __restrict__ attn,
                                const void* __restrict__ ids_raw) {
    extern __shared__ float row[];
    __shared__ float red[32];
    __shared__ float s_bcast;

    const int b = blockIdx.x;
    const int tid = threadIdx.x;   // 1024
    float* o = out + (size_t)b * NV;

    float m = -INFINITY;
    for (int v = tid; v < NV; v += 1024) {
        float t = o[v];
        row[v] = t;
        m = fmaxf(m, t);
    }
    m = warp_reduce_max(m);
    if ((tid & 31) == 0) red[tid >> 5] = m;
    __syncthreads();
    if (tid < 32) {
        float t = warp_reduce_max(red[tid]);
        if (tid == 0) s_bcast = t;
    }
    __syncthreads();
    m = s_bcast;

    float sum = 0.f;
    for (int v = tid; v < NV; v += 1024) {
        float e = __expf(row[v] - m);
        row[v] = e;
        sum += e;
    }
    sum = warp_reduce_sum(sum);
    __syncthreads();
    if ((tid & 31) == 0) red[tid >> 5] = sum;
    __syncthreads();
    if (tid < 32) {
        float t = warp_reduce_sum(red[tid]);
        if (tid == 0) s_bcast = t;
    }
    __syncthreads();
    sum = s_bcast;

    const float pg = g_pgen[b];
    const float scale = pg / sum;

    for (int v = tid; v < NV; v += 1024) row[v] *= scale;
    __syncthreads();

    if (tid < NS) {
        int id;
        if (g_ids_is64)
            id = (int)reinterpret_cast<const long long*>(ids_raw)[(size_t)b * NS + tid];
        else
            id = reinterpret_cast<const int*>(ids_raw)[(size_t)b * NS + tid];
        atomicAdd(&row[id], (1.f - pg) * attn[b * NS + tid]);
    }
    __syncthreads();

    for (int v = tid; v < NV; v += 1024) o[v] = logf(row[v] + 1e-40f);
}

// ---------------------------------------------------------------------------
// Launch
// ---------------------------------------------------------------------------
extern "C" void kernel_launch(void* const* d_in, const int* in_sizes, int n_in,
                              void* d_out, int out_size) {
    const float* x      = (const float*)d_in[0];
    const float* embed  = (const float*)d_in[1];
    const float* hidden = (const float*)d_in[2];
    const float* enc    = (const float*)d_in[3];
    const float* attn   = (const float*)d_in[4];
    const void*  ids    = d_in[5];
    const float* proj_w = (const float*)d_in[6];
    const float* proj_b = (const float*)d_in[7];
    const float* pgen_w = (const float*)d_in[8];
    const float* pgen_b = (const float*)d_in[9];
    float* out = (float*)d_out;

    detect_ids_kernel<<<1, 256>>>((const int*)ids);

    dim3 gctx(NB, SCHUNKS);
    ctx_partial_kernel<<<gctx, 256>>>(attn, enc, pgen_w);
    pgen_kernel<<<NB, 256>>>(hidden, embed, pgen_w, pgen_b);

    cudaFuncSetAttribute(gemm_mma_kernel,
                         cudaFuncAttributeMaxDynamicSharedMemorySize, GSMEM);
    dim3 gg(NB / BM, (NV + BN - 1) / BN);   // (2, 393): M-halves adjacent -> L2 reuse of W
    gemm_mma_kernel<<<gg, 256, GSMEM>>>(x, proj_w, proj_b, out);

    const int smem_bytes = NV * sizeof(float);
    cudaFuncSetAttribute(finalize_kernel,
                         cudaFuncAttributeMaxDynamicSharedMemorySize, smem_bytes);
    finalize_kernel<<<NB, 1024, smem_bytes>>>(out, attn, ids);
}